// round 2
// baseline (speedup 1.0000x reference)
#include <cuda_runtime.h>
#include <cuda_bf16.h>

#define BB   4
#define NQ   512
#define NK   512
#define DD   512
#define HH   128

#define TQ   8      // queries per score-block
#define TK   32     // keys per score-tile
#define HPAD 132    // 128 + 4 pad: conflict-free LDS.128 across k-lanes

// scratch (allocation-free: device globals)
__device__ float g_Qp[BB * NQ * HH];
__device__ float g_Kp[BB * NK * HH];
__device__ float g_P [BB * NQ * NK];

__device__ __forceinline__ float fast_tanh(float x) {
    float y;
    asm("tanh.approx.f32 %0, %1;" : "=f"(y) : "f"(x));
    return y;
}

// Robust valid_lens read: reference dtype is int64, but the harness may store
// int32. Values are in [1, NK] (>=1 always), so viewing the first 16 bytes as
// 4x int32: int64 layout gives [a,0,b,0]; int32 layout gives [a,b,c,d] all >=1.
__device__ __forceinline__ long long read_vlen(const void* p, int b) {
    const int* w = (const int*)p;
    bool is64 = (w[1] == 0) && (w[3] == 0);
    if (is64) return ((const long long*)p)[b];
    return (long long)w[b];
}

// ---------------------------------------------------------------------------
// Generic row-major GEMM: C = A(MxK) @ B(KxN), batched via blockIdx.z.
// BM=BN=64, BK=16, 256 threads, 4x4 micro-tile per thread.
// ---------------------------------------------------------------------------
__global__ __launch_bounds__(256)
void gemm_rrr(const float* __restrict__ A, const float* __restrict__ Bm,
              float* __restrict__ C, int M, int N, int K,
              long long sA, long long sB, long long sC)
{
    const int batch = blockIdx.z;
    A  += (long long)batch * sA;
    Bm += (long long)batch * sB;
    C  += (long long)batch * sC;

    __shared__ float As[16][68];   // transposed A tile: As[k][m]
    __shared__ float Bs[16][68];   // Bs[k][n]

    const int tid = threadIdx.x;
    const int tx  = tid & 15;
    const int ty  = tid >> 4;
    const int m0  = blockIdx.y * 64;
    const int n0  = blockIdx.x * 64;

    const int arow = tid >> 2;
    const int ak4  = (tid & 3) * 4;
    const int bk   = tid >> 4;
    const int bn4  = (tid & 15) * 4;

    float acc[4][4];
#pragma unroll
    for (int i = 0; i < 4; i++)
#pragma unroll
        for (int j = 0; j < 4; j++) acc[i][j] = 0.f;

    for (int k0 = 0; k0 < K; k0 += 16) {
        float4 av = *(const float4*)&A[(long long)(m0 + arow) * K + k0 + ak4];
        float4 bv = *(const float4*)&Bm[(long long)(k0 + bk) * N + n0 + bn4];

        As[ak4 + 0][arow] = av.x;
        As[ak4 + 1][arow] = av.y;
        As[ak4 + 2][arow] = av.z;
        As[ak4 + 3][arow] = av.w;
        *(float4*)&Bs[bk][bn4] = bv;
        __syncthreads();

#pragma unroll
        for (int kk = 0; kk < 16; kk++) {
            float4 a = *(const float4*)&As[kk][ty * 4];
            float4 b = *(const float4*)&Bs[kk][tx * 4];
            acc[0][0] += a.x * b.x; acc[0][1] += a.x * b.y; acc[0][2] += a.x * b.z; acc[0][3] += a.x * b.w;
            acc[1][0] += a.y * b.x; acc[1][1] += a.y * b.y; acc[1][2] += a.y * b.z; acc[1][3] += a.y * b.w;
            acc[2][0] += a.z * b.x; acc[2][1] += a.z * b.y; acc[2][2] += a.z * b.z; acc[2][3] += a.z * b.w;
            acc[3][0] += a.w * b.x; acc[3][1] += a.w * b.y; acc[3][2] += a.w * b.z; acc[3][3] += a.w * b.w;
        }
        __syncthreads();
    }

#pragma unroll
    for (int i = 0; i < 4; i++) {
        float4 out = make_float4(acc[i][0], acc[i][1], acc[i][2], acc[i][3]);
        *(float4*)&C[(long long)(m0 + ty * 4 + i) * N + n0 + tx * 4] = out;
    }
}

// ---------------------------------------------------------------------------
// Fused scores + mask + softmax.
// Block = TQ=8 query rows of one batch, over all NK=512 keys.
// scores[q][k] = sum_h wv[h] * tanh(Qp[q][h] + Kp[k][h]); mask; softmax -> P.
// ---------------------------------------------------------------------------
__global__ __launch_bounds__(256)
void scores_softmax(const float* __restrict__ Qp, const float* __restrict__ Kp,
                    const float* __restrict__ wv, const void* __restrict__ vlen,
                    float* __restrict__ P)
{
    __shared__ float qps[TQ][HPAD];
    __shared__ float kps[TK][HPAD];
    __shared__ float wvs[HH];
    __shared__ float s[TQ][NK];

    const int tid = threadIdx.x;
    const int bx  = blockIdx.x;
    const int b   = bx / (NQ / TQ);
    const int q0  = (bx % (NQ / TQ)) * TQ;

    if (tid < HH) wvs[tid] = wv[tid];

    {
        const int q  = tid >> 5;
        const int h4 = (tid & 31) * 4;
        float4 v = *(const float4*)&Qp[(long long)(b * NQ + q0 + q) * HH + h4];
        *(float4*)&qps[q][h4] = v;
    }

    const int q = tid >> 5;
    const int k = tid & 31;

    for (int kt = 0; kt < NK / TK; kt++) {
        __syncthreads();
#pragma unroll
        for (int r = 0; r < 4; r++) {
            int i  = tid + 256 * r;
            int kk = i >> 5;
            int h4 = (i & 31) * 4;
            float4 v = *(const float4*)&Kp[(long long)(b * NK + kt * TK + kk) * HH + h4];
            *(float4*)&kps[kk][h4] = v;
        }
        __syncthreads();

        float acc = 0.f;
#pragma unroll 8
        for (int h4 = 0; h4 < HH / 4; h4++) {
            float4 kv = *(const float4*)&kps[k][h4 * 4];
            float4 qv = *(const float4*)&qps[q][h4 * 4];
            float4 w  = *(const float4*)&wvs[h4 * 4];
            acc += w.x * fast_tanh(qv.x + kv.x);
            acc += w.y * fast_tanh(qv.y + kv.y);
            acc += w.z * fast_tanh(qv.z + kv.z);
            acc += w.w * fast_tanh(qv.w + kv.w);
        }
        s[q][kt * TK + k] = acc;
    }
    __syncthreads();

    // softmax: warp q owns row q
    const int       lane = k;
    const long long vl   = read_vlen(vlen, b);

    float m = -1e30f;
    for (int j = lane; j < NK; j += 32) {
        float x = (j < vl) ? s[q][j] : -1e20f;
        m = fmaxf(m, x);
    }
#pragma unroll
    for (int o = 16; o > 0; o >>= 1) m = fmaxf(m, __shfl_xor_sync(0xffffffffu, m, o));

    float sum = 0.f;
    for (int j = lane; j < NK; j += 32) {
        float x = (j < vl) ? s[q][j] : -1e20f;
        float e = __expf(x - m);
        s[q][j] = e;
        sum += e;
    }
#pragma unroll
    for (int o = 16; o > 0; o >>= 1) sum += __shfl_xor_sync(0xffffffffu, sum, o);

    const float inv = 1.f / sum;
    float* prow = &P[(long long)(b * NQ + q0 + q) * NK];
    for (int j = lane; j < NK; j += 32) prow[j] = s[q][j] * inv;
}

// ---------------------------------------------------------------------------
extern "C" void kernel_launch(void* const* d_in, const int* in_sizes, int n_in,
                              void* d_out, int out_size)
{
    const float* Q    = (const float*)d_in[0];
    const float* K    = (const float*)d_in[1];
    const float* V    = (const float*)d_in[2];
    const float* Wq   = (const float*)d_in[3];
    const float* Wk   = (const float*)d_in[4];
    const float* wv   = (const float*)d_in[5];
    const void*  vlen = (const void*)d_in[6];
    float*       out  = (float*)d_out;

    float *pQp, *pKp, *pP;
    cudaGetSymbolAddress((void**)&pQp, g_Qp);
    cudaGetSymbolAddress((void**)&pKp, g_Kp);
    cudaGetSymbolAddress((void**)&pP,  g_P);

    // 1) Qp = Q @ Wq   (M=2048, N=128, K=512)
    {
        dim3 grid(HH / 64, (BB * NQ) / 64, 1);
        gemm_rrr<<<grid, 256>>>(Q, Wq, pQp, BB * NQ, HH, DD, 0, 0, 0);
    }
    // 2) Kp = K @ Wk
    {
        dim3 grid(HH / 64, (BB * NK) / 64, 1);
        gemm_rrr<<<grid, 256>>>(K, Wk, pKp, BB * NK, HH, DD, 0, 0, 0);
    }
    // 3) scores + mask + softmax -> P
    {
        dim3 grid(BB * NQ / TQ);
        scores_softmax<<<grid, 256>>>(pQp, pKp, wv, vlen, pP);
    }
    // 4) out = P @ V   (batched 4 x [512x512]@[512x512])
    {
        dim3 grid(DD / 64, NQ / 64, BB);
        gemm_rrr<<<grid, 256>>>(pP, V, out, NQ, DD, NK,
                                (long long)NQ * NK, (long long)NK * DD,
                                (long long)NQ * DD);
    }
}

// round 3
// speedup vs baseline: 1.0014x; 1.0014x over previous
#include <cuda_runtime.h>
#include <cuda_bf16.h>

#define BB   4
#define NQ   512
#define NK   512
#define DD   512
#define HH   128

#define TQ   8      // queries per score-block
#define TK   32     // keys per score-tile
#define HPAD 132    // 128 + 4 pad: conflict-free LDS.128 across k-lanes

// scratch (allocation-free: device globals)
__device__ float g_Qp[BB * NQ * HH];
__device__ float g_Kp[BB * NK * HH];
__device__ float g_P [BB * NQ * NK];

__device__ __forceinline__ float fast_tanh(float x) {
    float y;
    asm("tanh.approx.f32 %0, %1;" : "=f"(y) : "f"(x));
    return y;
}

// Robust valid_lens read: reference dtype is int64, but the harness may store
// int32. Values are in [1, NK] (>=1 always), so viewing the first 16 bytes as
// 4x int32: int64 layout gives [a,0,b,0]; int32 layout gives [a,b,c,d] all >=1.
__device__ __forceinline__ long long read_vlen(const void* p, int b) {
    const int* w = (const int*)p;
    bool is64 = (w[1] == 0) && (w[3] == 0);
    if (is64) return ((const long long*)p)[b];
    return (long long)w[b];
}

// ---------------------------------------------------------------------------
// Generic row-major GEMM: C = A(MxK) @ B(KxN), batched via blockIdx.z.
// BM=BN=64, BK=16, 256 threads, 4x4 micro-tile per thread.
// ---------------------------------------------------------------------------
__global__ __launch_bounds__(256)
void gemm_rrr(const float* __restrict__ A, const float* __restrict__ Bm,
              float* __restrict__ C, int M, int N, int K,
              long long sA, long long sB, long long sC)
{
    const int batch = blockIdx.z;
    A  += (long long)batch * sA;
    Bm += (long long)batch * sB;
    C  += (long long)batch * sC;

    __shared__ float As[16][68];   // transposed A tile: As[k][m]
    __shared__ float Bs[16][68];   // Bs[k][n]

    const int tid = threadIdx.x;
    const int tx  = tid & 15;
    const int ty  = tid >> 4;
    const int m0  = blockIdx.y * 64;
    const int n0  = blockIdx.x * 64;

    const int arow = tid >> 2;
    const int ak4  = (tid & 3) * 4;
    const int bk   = tid >> 4;
    const int bn4  = (tid & 15) * 4;

    float acc[4][4];
#pragma unroll
    for (int i = 0; i < 4; i++)
#pragma unroll
        for (int j = 0; j < 4; j++) acc[i][j] = 0.f;

    for (int k0 = 0; k0 < K; k0 += 16) {
        float4 av = *(const float4*)&A[(long long)(m0 + arow) * K + k0 + ak4];
        float4 bv = *(const float4*)&Bm[(long long)(k0 + bk) * N + n0 + bn4];

        As[ak4 + 0][arow] = av.x;
        As[ak4 + 1][arow] = av.y;
        As[ak4 + 2][arow] = av.z;
        As[ak4 + 3][arow] = av.w;
        *(float4*)&Bs[bk][bn4] = bv;
        __syncthreads();

#pragma unroll
        for (int kk = 0; kk < 16; kk++) {
            float4 a = *(const float4*)&As[kk][ty * 4];
            float4 b = *(const float4*)&Bs[kk][tx * 4];
            acc[0][0] += a.x * b.x; acc[0][1] += a.x * b.y; acc[0][2] += a.x * b.z; acc[0][3] += a.x * b.w;
            acc[1][0] += a.y * b.x; acc[1][1] += a.y * b.y; acc[1][2] += a.y * b.z; acc[1][3] += a.y * b.w;
            acc[2][0] += a.z * b.x; acc[2][1] += a.z * b.y; acc[2][2] += a.z * b.z; acc[2][3] += a.z * b.w;
            acc[3][0] += a.w * b.x; acc[3][1] += a.w * b.y; acc[3][2] += a.w * b.z; acc[3][3] += a.w * b.w;
        }
        __syncthreads();
    }

#pragma unroll
    for (int i = 0; i < 4; i++) {
        float4 out = make_float4(acc[i][0], acc[i][1], acc[i][2], acc[i][3]);
        *(float4*)&C[(long long)(m0 + ty * 4 + i) * N + n0 + tx * 4] = out;
    }
}

// ---------------------------------------------------------------------------
// Fused scores + mask + softmax.
// Block = TQ=8 query rows of one batch, over all NK=512 keys.
// scores[q][k] = sum_h wv[h] * tanh(Qp[q][h] + Kp[k][h]); mask; softmax -> P.
// ---------------------------------------------------------------------------
__global__ __launch_bounds__(256)
void scores_softmax(const float* __restrict__ Qp, const float* __restrict__ Kp,
                    const float* __restrict__ wv, const void* __restrict__ vlen,
                    float* __restrict__ P)
{
    __shared__ float qps[TQ][HPAD];
    __shared__ float kps[TK][HPAD];
    __shared__ float wvs[HH];
    __shared__ float s[TQ][NK];

    const int tid = threadIdx.x;
    const int bx  = blockIdx.x;
    const int b   = bx / (NQ / TQ);
    const int q0  = (bx % (NQ / TQ)) * TQ;

    if (tid < HH) wvs[tid] = wv[tid];

    {
        const int q  = tid >> 5;
        const int h4 = (tid & 31) * 4;
        float4 v = *(const float4*)&Qp[(long long)(b * NQ + q0 + q) * HH + h4];
        *(float4*)&qps[q][h4] = v;
    }

    const int q = tid >> 5;
    const int k = tid & 31;

    for (int kt = 0; kt < NK / TK; kt++) {
        __syncthreads();
#pragma unroll
        for (int r = 0; r < 4; r++) {
            int i  = tid + 256 * r;
            int kk = i >> 5;
            int h4 = (i & 31) * 4;
            float4 v = *(const float4*)&Kp[(long long)(b * NK + kt * TK + kk) * HH + h4];
            *(float4*)&kps[kk][h4] = v;
        }
        __syncthreads();

        float acc = 0.f;
#pragma unroll 8
        for (int h4 = 0; h4 < HH / 4; h4++) {
            float4 kv = *(const float4*)&kps[k][h4 * 4];
            float4 qv = *(const float4*)&qps[q][h4 * 4];
            float4 w  = *(const float4*)&wvs[h4 * 4];
            acc += w.x * fast_tanh(qv.x + kv.x);
            acc += w.y * fast_tanh(qv.y + kv.y);
            acc += w.z * fast_tanh(qv.z + kv.z);
            acc += w.w * fast_tanh(qv.w + kv.w);
        }
        s[q][kt * TK + k] = acc;
    }
    __syncthreads();

    // softmax: warp q owns row q
    const int       lane = k;
    const long long vl   = read_vlen(vlen, b);

    float m = -1e30f;
    for (int j = lane; j < NK; j += 32) {
        float x = (j < vl) ? s[q][j] : -1e20f;
        m = fmaxf(m, x);
    }
#pragma unroll
    for (int o = 16; o > 0; o >>= 1) m = fmaxf(m, __shfl_xor_sync(0xffffffffu, m, o));

    float sum = 0.f;
    for (int j = lane; j < NK; j += 32) {
        float x = (j < vl) ? s[q][j] : -1e20f;
        float e = __expf(x - m);
        s[q][j] = e;
        sum += e;
    }
#pragma unroll
    for (int o = 16; o > 0; o >>= 1) sum += __shfl_xor_sync(0xffffffffu, sum, o);

    const float inv = 1.f / sum;
    float* prow = &P[(long long)(b * NQ + q0 + q) * NK];
    for (int j = lane; j < NK; j += 32) prow[j] = s[q][j] * inv;
}

// ---------------------------------------------------------------------------
extern "C" void kernel_launch(void* const* d_in, const int* in_sizes, int n_in,
                              void* d_out, int out_size)
{
    const float* Q    = (const float*)d_in[0];
    const float* K    = (const float*)d_in[1];
    const float* V    = (const float*)d_in[2];
    const float* Wq   = (const float*)d_in[3];
    const float* Wk   = (const float*)d_in[4];
    const float* wv   = (const float*)d_in[5];
    const void*  vlen = (const void*)d_in[6];
    float*       out  = (float*)d_out;

    float *pQp, *pKp, *pP;
    cudaGetSymbolAddress((void**)&pQp, g_Qp);
    cudaGetSymbolAddress((void**)&pKp, g_Kp);
    cudaGetSymbolAddress((void**)&pP,  g_P);

    // 1) Qp = Q @ Wq   (M=2048, N=128, K=512)
    {
        dim3 grid(HH / 64, (BB * NQ) / 64, 1);
        gemm_rrr<<<grid, 256>>>(Q, Wq, pQp, BB * NQ, HH, DD, 0, 0, 0);
    }
    // 2) Kp = K @ Wk
    {
        dim3 grid(HH / 64, (BB * NK) / 64, 1);
        gemm_rrr<<<grid, 256>>>(K, Wk, pKp, BB * NK, HH, DD, 0, 0, 0);
    }
    // 3) scores + mask + softmax -> P
    {
        dim3 grid(BB * NQ / TQ);
        scores_softmax<<<grid, 256>>>(pQp, pKp, wv, vlen, pP);
    }
    // 4) out = P @ V   (batched 4 x [512x512]@[512x512])
    {
        dim3 grid(DD / 64, NQ / 64, BB);
        gemm_rrr<<<grid, 256>>>(pP, V, out, NQ, DD, NK,
                                (long long)NQ * NK, (long long)NK * DD,
                                (long long)NQ * DD);
    }
}

// round 4
// speedup vs baseline: 1.3696x; 1.3677x over previous
#include <cuda_runtime.h>
#include <cuda_bf16.h>

#define BB   4
#define NQ   512
#define NK   512
#define DD   512
#define HH   128

#define TQ   8
#define TK   32
#define HPAD 132

__device__ float g_Qp[BB * NQ * HH];
__device__ float g_Kp[BB * NK * HH];
__device__ float g_P [BB * NQ * NK];

__device__ __forceinline__ float fast_tanh(float x) {
    float y;
    asm("tanh.approx.f32 %0, %1;" : "=f"(y) : "f"(x));
    return y;
}

__device__ __forceinline__ long long read_vlen(const void* p, int b) {
    const int* w = (const int*)p;
    bool is64 = (w[1] == 0) && (w[3] == 0);
    if (is64) return ((const long long*)p)[b];
    return (long long)w[b];
}

// ---------------------------------------------------------------------------
// Double-buffered 64x64x16 GEMM body, 256 threads, 4x4 microtile.
// C[m0:m0+64, n0:n0+64] = A(MxK) @ B(KxN) tile. K % 16 == 0.
// ---------------------------------------------------------------------------
__device__ __forceinline__ void gemm64_db(const float* __restrict__ A,
                                          const float* __restrict__ B,
                                          float* __restrict__ C,
                                          int M, int N, int K,
                                          int m0, int n0)
{
    __shared__ float As[2][16][68];
    __shared__ float Bs[2][16][68];

    const int tid  = threadIdx.x;
    const int tx   = tid & 15;
    const int ty   = tid >> 4;
    const int arow = tid >> 2;
    const int ak4  = (tid & 3) << 2;
    const int bk   = tid >> 4;
    const int bn4  = (tid & 15) << 2;

    const float* Aptr = A + (long long)(m0 + arow) * K + ak4;
    const float* Bptr = B + (long long)bk * N + n0 + bn4;

    float acc[4][4];
#pragma unroll
    for (int i = 0; i < 4; i++)
#pragma unroll
        for (int j = 0; j < 4; j++) acc[i][j] = 0.f;

    // prologue: tile 0 -> buffer 0
    {
        float4 av = *(const float4*)Aptr;
        float4 bv = *(const float4*)Bptr;
        As[0][ak4 + 0][arow] = av.x;
        As[0][ak4 + 1][arow] = av.y;
        As[0][ak4 + 2][arow] = av.z;
        As[0][ak4 + 3][arow] = av.w;
        *(float4*)&Bs[0][bk][bn4] = bv;
    }
    __syncthreads();

    const int nt = K >> 4;
    for (int t = 0; t < nt; t++) {
        const int cur = t & 1;
        const int nxt = cur ^ 1;

        float4 av2, bv2;
        const bool more = (t + 1 < nt);
        if (more) {
            av2 = *(const float4*)(Aptr + (t + 1) * 16);
            bv2 = *(const float4*)(Bptr + (long long)(t + 1) * 16 * N);
        }

#pragma unroll
        for (int kk = 0; kk < 16; kk++) {
            float4 a = *(const float4*)&As[cur][kk][ty * 4];
            float4 b = *(const float4*)&Bs[cur][kk][tx * 4];
            acc[0][0] += a.x * b.x; acc[0][1] += a.x * b.y; acc[0][2] += a.x * b.z; acc[0][3] += a.x * b.w;
            acc[1][0] += a.y * b.x; acc[1][1] += a.y * b.y; acc[1][2] += a.y * b.z; acc[1][3] += a.y * b.w;
            acc[2][0] += a.z * b.x; acc[2][1] += a.z * b.y; acc[2][2] += a.z * b.z; acc[2][3] += a.z * b.w;
            acc[3][0] += a.w * b.x; acc[3][1] += a.w * b.y; acc[3][2] += a.w * b.z; acc[3][3] += a.w * b.w;
        }

        if (more) {
            As[nxt][ak4 + 0][arow] = av2.x;
            As[nxt][ak4 + 1][arow] = av2.y;
            As[nxt][ak4 + 2][arow] = av2.z;
            As[nxt][ak4 + 3][arow] = av2.w;
            *(float4*)&Bs[nxt][bk][bn4] = bv2;
        }
        __syncthreads();
    }

#pragma unroll
    for (int i = 0; i < 4; i++) {
        float4 out = make_float4(acc[i][0], acc[i][1], acc[i][2], acc[i][3]);
        *(float4*)&C[(long long)(m0 + ty * 4 + i) * N + n0 + tx * 4] = out;
    }
}

// Both projections in ONE launch: z=0 -> Qp = Q@Wq, z=1 -> Kp = K@Wk.
__global__ __launch_bounds__(256)
void proj_gemm(const float* __restrict__ Q, const float* __restrict__ Kin,
               const float* __restrict__ Wq, const float* __restrict__ Wk,
               float* __restrict__ Qp, float* __restrict__ Kp)
{
    const float* A = blockIdx.z ? Kin : Q;
    const float* W = blockIdx.z ? Wk  : Wq;
    float*       C = blockIdx.z ? Kp  : Qp;
    gemm64_db(A, W, C, BB * NQ, HH, DD, blockIdx.y * 64, blockIdx.x * 64);
}

// Batched PV GEMM: out[b] = P[b] @ V[b]
__global__ __launch_bounds__(256)
void pv_gemm(const float* __restrict__ P, const float* __restrict__ V,
             float* __restrict__ out)
{
    const int b = blockIdx.z;
    gemm64_db(P + (long long)b * NQ * NK,
              V + (long long)b * NK * DD,
              out + (long long)b * NQ * DD,
              NQ, DD, NK, blockIdx.y * 64, blockIdx.x * 64);
}

// ---------------------------------------------------------------------------
// Fused scores + mask + softmax (double-buffered K tiles).
// ---------------------------------------------------------------------------
__global__ __launch_bounds__(256)
void scores_softmax(const float* __restrict__ Qp, const float* __restrict__ Kp,
                    const float* __restrict__ wv, const void* __restrict__ vlen,
                    float* __restrict__ P)
{
    __shared__ float qps[TQ][HPAD];
    __shared__ float kps[2][TK][HPAD];
    __shared__ float wvs[HH];
    __shared__ float s[TQ][NK];

    const int tid = threadIdx.x;
    const int bx  = blockIdx.x;
    const int b   = bx / (NQ / TQ);
    const int q0  = (bx % (NQ / TQ)) * TQ;

    if (tid < HH) wvs[tid] = wv[tid];

    {
        const int q  = tid >> 5;
        const int h4 = (tid & 31) * 4;
        float4 v = *(const float4*)&Qp[(long long)(b * NQ + q0 + q) * HH + h4];
        *(float4*)&qps[q][h4] = v;
    }

    const int q = tid >> 5;
    const int k = tid & 31;

    const float* kbase = &Kp[(long long)b * NK * HH];
    const int lrow = tid >> 5;          // 0..7 (row block within tile, +8 per r)
    const int lh4  = (tid & 31) * 4;

    // prologue: kt=0 tile into buffer 0
#pragma unroll
    for (int r = 0; r < 4; r++) {
        int kk = lrow + 8 * r;
        float4 v = *(const float4*)&kbase[(long long)kk * HH + lh4];
        *(float4*)&kps[0][kk][lh4] = v;
    }
    __syncthreads();

    const int NT = NK / TK;
    for (int kt = 0; kt < NT; kt++) {
        const int cur = kt & 1;
        const int nxt = cur ^ 1;
        float4 pre[4];
        const bool more = (kt + 1 < NT);
        if (more) {
#pragma unroll
            for (int r = 0; r < 4; r++) {
                int kk = lrow + 8 * r;
                pre[r] = *(const float4*)&kbase[(long long)((kt + 1) * TK + kk) * HH + lh4];
            }
        }

        float acc = 0.f;
#pragma unroll 8
        for (int h4 = 0; h4 < HH / 4; h4++) {
            float4 kv = *(const float4*)&kps[cur][k][h4 * 4];
            float4 qv = *(const float4*)&qps[q][h4 * 4];
            float4 w  = *(const float4*)&wvs[h4 * 4];
            acc += w.x * fast_tanh(qv.x + kv.x);
            acc += w.y * fast_tanh(qv.y + kv.y);
            acc += w.z * fast_tanh(qv.z + kv.z);
            acc += w.w * fast_tanh(qv.w + kv.w);
        }
        s[q][kt * TK + k] = acc;

        if (more) {
#pragma unroll
            for (int r = 0; r < 4; r++) {
                int kk = lrow + 8 * r;
                *(float4*)&kps[nxt][kk][lh4] = pre[r];
            }
        }
        __syncthreads();
    }

    // softmax: warp q owns row q
    const int       lane = k;
    const long long vl   = read_vlen(vlen, b);

    float m = -1e30f;
    for (int j = lane; j < NK; j += 32) {
        float x = (j < vl) ? s[q][j] : -1e20f;
        m = fmaxf(m, x);
    }
#pragma unroll
    for (int o = 16; o > 0; o >>= 1) m = fmaxf(m, __shfl_xor_sync(0xffffffffu, m, o));

    float sum = 0.f;
    for (int j = lane; j < NK; j += 32) {
        float x = (j < vl) ? s[q][j] : -1e20f;
        float e = __expf(x - m);
        s[q][j] = e;
        sum += e;
    }
#pragma unroll
    for (int o = 16; o > 0; o >>= 1) sum += __shfl_xor_sync(0xffffffffu, sum, o);

    const float inv = 1.f / sum;
    float* prow = &P[(long long)(b * NQ + q0 + q) * NK];
    for (int j = lane; j < NK; j += 32) prow[j] = s[q][j] * inv;
}

// ---------------------------------------------------------------------------
extern "C" void kernel_launch(void* const* d_in, const int* in_sizes, int n_in,
                              void* d_out, int out_size)
{
    const float* Q    = (const float*)d_in[0];
    const float* K    = (const float*)d_in[1];
    const float* V    = (const float*)d_in[2];
    const float* Wq   = (const float*)d_in[3];
    const float* Wk   = (const float*)d_in[4];
    const float* wv   = (const float*)d_in[5];
    const void*  vlen = (const void*)d_in[6];
    float*       out  = (float*)d_out;

    float *pQp, *pKp, *pP;
    cudaGetSymbolAddress((void**)&pQp, g_Qp);
    cudaGetSymbolAddress((void**)&pKp, g_Kp);
    cudaGetSymbolAddress((void**)&pP,  g_P);

    // 1) Qp = Q@Wq and Kp = K@Wk in one full-chip launch (128 blocks)
    {
        dim3 grid(HH / 64, (BB * NQ) / 64, 2);
        proj_gemm<<<grid, 256>>>(Q, K, Wq, Wk, pQp, pKp);
    }
    // 2) scores + mask + softmax -> P
    {
        dim3 grid(BB * NQ / TQ);
        scores_softmax<<<grid, 256>>>(pQp, pKp, wv, vlen, pP);
    }
    // 3) out = P @ V (batched, 256 blocks)
    {
        dim3 grid(DD / 64, NQ / 64, BB);
        pv_gemm<<<grid, 256>>>(pP, V, out);
    }
}

// round 6
// speedup vs baseline: 1.7789x; 1.2988x over previous
#include <cuda_runtime.h>
#include <cuda_bf16.h>
#include <cstdint>

#define BB   4
#define NQ   512
#define NK   512
#define DD   512
#define HH   128

#define TQ   8
#define TK   32
#define HPAD 132

// ---------------- scratch (allocation-free device globals) ----------------
__device__ float g_Qp[BB * NQ * HH];
__device__ float g_Kp[BB * NK * HH];
__device__ __nv_bfloat16 g_Qh[BB * NQ * DD], g_Ql[BB * NQ * DD];
__device__ __nv_bfloat16 g_Kh[BB * NK * DD], g_Kl[BB * NK * DD];
__device__ __nv_bfloat16 g_Wqth[HH * DD], g_Wqtl[HH * DD];   // W^T [128][512]
__device__ __nv_bfloat16 g_Wkth[HH * DD], g_Wktl[HH * DD];
__device__ __nv_bfloat16 g_Vth[BB * DD * NK], g_Vtl[BB * DD * NK]; // V^T [n][k]
__device__ __nv_bfloat16 g_Ph[BB * NQ * NK], g_Pl[BB * NQ * NK];

__device__ __forceinline__ float fast_tanh(float x) {
    float y;
    asm("tanh.approx.f32 %0, %1;" : "=f"(y) : "f"(x));
    return y;
}

__device__ __forceinline__ long long read_vlen(const void* p, int b) {
    const int* w = (const int*)p;
    bool is64 = (w[1] == 0) && (w[3] == 0);
    if (is64) return ((const long long*)p)[b];
    return (long long)w[b];
}

__device__ __forceinline__ uint32_t smem_u32(const void* p) {
    uint32_t a;
    asm("{ .reg .u64 t; cvta.to.shared.u64 t, %1; cvt.u32.u64 %0, t; }" : "=r"(a) : "l"(p));
    return a;
}

__device__ __forceinline__ void ldmx4(uint32_t* r, uint32_t addr) {
    asm volatile("ldmatrix.sync.aligned.m8n8.x4.shared.b16 {%0,%1,%2,%3}, [%4];"
        : "=r"(r[0]), "=r"(r[1]), "=r"(r[2]), "=r"(r[3]) : "r"(addr));
}

__device__ __forceinline__ void mma16816(float* d, const uint32_t* a, const uint32_t* b) {
    asm volatile("mma.sync.aligned.m16n8k16.row.col.f32.bf16.bf16.f32 "
        "{%0,%1,%2,%3}, {%4,%5,%6,%7}, {%8,%9}, {%0,%1,%2,%3};"
        : "+f"(d[0]), "+f"(d[1]), "+f"(d[2]), "+f"(d[3])
        : "r"(a[0]), "r"(a[1]), "r"(a[2]), "r"(a[3]), "r"(b[0]), "r"(b[1]));
}

// ---------------- conversion / transpose kernels ----------------
__global__ void split_qk(const float* __restrict__ Q, const float* __restrict__ K)
{
    const float* in = blockIdx.z ? K : Q;
    __nv_bfloat16* hi = blockIdx.z ? g_Kh : g_Qh;
    __nv_bfloat16* lo = blockIdx.z ? g_Kl : g_Ql;
    const int n4 = (BB * NQ * DD) / 4;
    for (int i = blockIdx.x * blockDim.x + threadIdx.x; i < n4; i += gridDim.x * blockDim.x) {
        float4 v = ((const float4*)in)[i];
        __nv_bfloat16 hx = __float2bfloat16(v.x), hy = __float2bfloat16(v.y);
        __nv_bfloat16 hz = __float2bfloat16(v.z), hw = __float2bfloat16(v.w);
        ((__nv_bfloat162*)hi)[i * 2 + 0] = __nv_bfloat162(hx, hy);
        ((__nv_bfloat162*)hi)[i * 2 + 1] = __nv_bfloat162(hz, hw);
        ((__nv_bfloat162*)lo)[i * 2 + 0] = __nv_bfloat162(
            __float2bfloat16(v.x - __bfloat162float(hx)), __float2bfloat16(v.y - __bfloat162float(hy)));
        ((__nv_bfloat162*)lo)[i * 2 + 1] = __nv_bfloat162(
            __float2bfloat16(v.z - __bfloat162float(hz)), __float2bfloat16(v.w - __bfloat162float(hw)));
    }
}

__global__ void wtrans(const float* __restrict__ Wq, const float* __restrict__ Wk)
{
    const float* W = blockIdx.z ? Wk : Wq;
    __nv_bfloat16* th = blockIdx.z ? g_Wkth : g_Wqth;
    __nv_bfloat16* tl = blockIdx.z ? g_Wktl : g_Wqtl;
    int i = blockIdx.x * blockDim.x + threadIdx.x;
    if (i < DD * HH) {
        int k = i >> 7, n = i & 127;
        float v = W[i];
        __nv_bfloat16 h = __float2bfloat16(v);
        th[n * DD + k] = h;
        tl[n * DD + k] = __float2bfloat16(v - __bfloat162float(h));
    }
}

// V[b][k][n] -> Vt[b][n][k]; skip k-tiles entirely beyond valid length.
__global__ void vtrans(const float* __restrict__ V, const void* __restrict__ vlen)
{
    __shared__ float t[32][33];
    const int b  = blockIdx.z;
    const int k0 = blockIdx.y * 32;
    if ((long long)k0 >= read_vlen(vlen, b)) return;
    const int n0 = blockIdx.x * 32;
    const int tx = threadIdx.x, ty = threadIdx.y;   // (32, 8)
    const float* Vb = V + (long long)b * NK * DD;
#pragma unroll
    for (int r = 0; r < 4; r++)
        t[ty + r * 8][tx] = Vb[(long long)(k0 + ty + r * 8) * DD + n0 + tx];
    __syncthreads();
    __nv_bfloat16* th = g_Vth + (long long)b * DD * NK;
    __nv_bfloat16* tl = g_Vtl + (long long)b * DD * NK;
#pragma unroll
    for (int r = 0; r < 4; r++) {
        float v = t[tx][ty + r * 8];
        __nv_bfloat16 h = __float2bfloat16(v);
        th[(long long)(n0 + ty + r * 8) * NK + k0 + tx] = h;
        tl[(long long)(n0 + ty + r * 8) * NK + k0 + tx] = __float2bfloat16(v - __bfloat162float(h));
    }
}

// ---------------- warp-MMA bf16x3 GEMM: C[64x64] = A[64xK] @ B[64xK]^T -----
// A, B row-major K-major (ld in elements). 256 threads = 8 warps (4m x 2n).
// Rows padded to 80B in smem -> conflict-free ldmatrix.
#define STG  20480          // bytes per stage (4 tensors x 64 rows x 80B)
#define O_AH 0
#define O_AL 5120
#define O_BH 10240
#define O_BL 15360

__device__ __forceinline__ void mma_gemm(
    const __nv_bfloat16* __restrict__ Ah, const __nv_bfloat16* __restrict__ Al,
    const __nv_bfloat16* __restrict__ Bh, const __nv_bfloat16* __restrict__ Bl,
    float* __restrict__ C, int lda, int ldb, int ldc,
    int m0, int n0, int nstages)
{
    __shared__ __align__(128) char smem[2 * STG];
    const uint32_t sb = smem_u32(smem);
    const int tid  = threadIdx.x;
    const int lane = tid & 31;
    const int w    = tid >> 5;
    const int wm   = w & 3;     // 16-row slice
    const int wn   = w >> 2;    // 32-col slice

    // gmem load mapping: thread -> (row, 16B chunk)
    const int lrow = tid >> 2;
    const int lchk = tid & 3;
    const __nv_bfloat16* pAh = Ah + (long long)(m0 + lrow) * lda + lchk * 8;
    const __nv_bfloat16* pAl = Al + (long long)(m0 + lrow) * lda + lchk * 8;
    const __nv_bfloat16* pBh = Bh + (long long)(n0 + lrow) * ldb + lchk * 8;
    const __nv_bfloat16* pBl = Bl + (long long)(n0 + lrow) * ldb + lchk * 8;
    const uint32_t stO = lrow * 80 + lchk * 16;

    // ldmatrix lane addresses
    const uint32_t aOff = (wm * 16 + (lane & 15)) * 80 + (lane >> 4) * 16;
    const int jj = lane >> 3;
    const uint32_t bOff = (wn * 32 + (jj >> 1) * 8 + (lane & 7)) * 80 + (jj & 1) * 16;

    float acc[4][4] = {};

    // prologue: stage 0 -> buffer 0
    *(uint4*)(smem + O_AH + stO) = *(const uint4*)pAh;
    *(uint4*)(smem + O_AL + stO) = *(const uint4*)pAl;
    *(uint4*)(smem + O_BH + stO) = *(const uint4*)pBh;
    *(uint4*)(smem + O_BL + stO) = *(const uint4*)pBl;
    __syncthreads();

    for (int t = 0; t < nstages; t++) {
        const uint32_t cur = (uint32_t)(t & 1) * STG;
        const uint32_t nxt = cur ^ STG;
        uint4 rAh, rAl, rBh, rBl;
        const bool more = (t + 1 < nstages);
        if (more) {
            rAh = *(const uint4*)(pAh + (t + 1) * 32);
            rAl = *(const uint4*)(pAl + (t + 1) * 32);
            rBh = *(const uint4*)(pBh + (t + 1) * 32);
            rBl = *(const uint4*)(pBl + (t + 1) * 32);
        }
#pragma unroll
        for (int ks = 0; ks < 2; ks++) {
            uint32_t ah[4], al[4];
            ldmx4(ah, sb + cur + O_AH + aOff + ks * 32);
            ldmx4(al, sb + cur + O_AL + aOff + ks * 32);
#pragma unroll
            for (int np = 0; np < 2; np++) {
                uint32_t bh[4], bl[4];
                ldmx4(bh, sb + cur + O_BH + bOff + np * 1280 + ks * 32);
                ldmx4(bl, sb + cur + O_BL + bOff + np * 1280 + ks * 32);
                mma16816(acc[2 * np + 0], ah, bh);
                mma16816(acc[2 * np + 1], ah, bh + 2);
                mma16816(acc[2 * np + 0], ah, bl);
                mma16816(acc[2 * np + 1], ah, bl + 2);
                mma16816(acc[2 * np + 0], al, bh);
                mma16816(acc[2 * np + 1], al, bh + 2);
            }
        }
        if (more) {
            *(uint4*)(smem + nxt + O_AH + stO) = rAh;
            *(uint4*)(smem + nxt + O_AL + stO) = rAl;
            *(uint4*)(smem + nxt + O_BH + stO) = rBh;
            *(uint4*)(smem + nxt + O_BL + stO) = rBl;
        }
        __syncthreads();
    }

    const int rr = m0 + wm * 16 + (lane >> 2);
    const int cc = n0 + wn * 32 + (lane & 3) * 2;
#pragma unroll
    for (int nt = 0; nt < 4; nt++) {
        *(float2*)&C[(long long)rr * ldc + cc + nt * 8]       = make_float2(acc[nt][0], acc[nt][1]);
        *(float2*)&C[(long long)(rr + 8) * ldc + cc + nt * 8] = make_float2(acc[nt][2], acc[nt][3]);
    }
}

// z=0: Qp = Q@Wq (all rows); z=1: Kp = K@Wk (skip fully-masked row blocks)
__global__ __launch_bounds__(256)
void mma_proj(const void* __restrict__ vlen)
{
    const int n0 = blockIdx.x * 64;
    const int m0 = blockIdx.y * 64;
    if (blockIdx.z == 0) {
        mma_gemm(g_Qh, g_Ql, g_Wqth, g_Wqtl, g_Qp, DD, DD, HH, m0, n0, DD / 32);
    } else {
        if ((long long)(m0 & (NK - 1)) >= read_vlen(vlen, m0 >> 9)) return;
        mma_gemm(g_Kh, g_Kl, g_Wkth, g_Wktl, g_Kp, DD, DD, HH, m0, n0, DD / 32);
    }
}

// out[b] = P[b] @ V[b]; K-loop bounded by valid length (P==0 beyond).
__global__ __launch_bounds__(256)
void mma_pv(float* __restrict__ out, const void* __restrict__ vlen)
{
    const int b = blockIdx.z;
    const long long vl = read_vlen(vlen, b);
    const int ns = (int)((vl + 31) >> 5);
    mma_gemm(g_Ph + (long long)b * NQ * NK, g_Pl + (long long)b * NQ * NK,
             g_Vth + (long long)b * DD * NK, g_Vtl + (long long)b * DD * NK,
             out + (long long)b * NQ * DD,
             NK, NK, DD, blockIdx.y * 64, blockIdx.x * 64, ns);
}

// ---------------- fused scores + mask + softmax -> P (bf16 hi/lo) ----------
// Only computes k-tiles below the valid length.
__global__ __launch_bounds__(256)
void scores_softmax(const float* __restrict__ Qp, const float* __restrict__ Kp,
                    const float* __restrict__ wv, const void* __restrict__ vlen)
{
    __shared__ float qps[TQ][HPAD];
    __shared__ float kps[2][TK][HPAD];
    __shared__ float wvs[HH];
    __shared__ float s[TQ][NK];

    const int tid = threadIdx.x;
    const int bx  = blockIdx.x;
    const int b   = bx / (NQ / TQ);
    const int q0  = (bx % (NQ / TQ)) * TQ;

    const long long vl = read_vlen(vlen, b);
    const int NT = (int)((vl + TK - 1) / TK);   // active 32-key tiles

    if (tid < HH) wvs[tid] = wv[tid];

    {
        const int q  = tid >> 5;
        const int h4 = (tid & 31) * 4;
        float4 v = *(const float4*)&Qp[(long long)(b * NQ + q0 + q) * HH + h4];
        *(float4*)&qps[q][h4] = v;
    }

    const int q = tid >> 5;
    const int k = tid & 31;

    const float* kbase = &Kp[(long long)b * NK * HH];
    const int lrow = tid >> 5;
    const int lh4  = (tid & 31) * 4;

#pragma unroll
    for (int r = 0; r < 4; r++) {
        int kk = lrow + 8 * r;
        float4 v = *(const float4*)&kbase[(long long)kk * HH + lh4];
        *(float4*)&kps[0][kk][lh4] = v;
    }
    __syncthreads();

    for (int kt = 0; kt < NT; kt++) {
        const int cur = kt & 1;
        const int nxt = cur ^ 1;
        float4 pre[4];
        const bool more = (kt + 1 < NT);
        if (more) {
#pragma unroll
            for (int r = 0; r < 4; r++) {
                int kk = lrow + 8 * r;
                pre[r] = *(const float4*)&kbase[(long long)((kt + 1) * TK + kk) * HH + lh4];
            }
        }

        float acc = 0.f;
#pragma unroll 8
        for (int h4 = 0; h4 < HH / 4; h4++) {
            float4 kv = *(const float4*)&kps[cur][k][h4 * 4];
            float4 qv = *(const float4*)&qps[q][h4 * 4];
            float4 w  = *(const float4*)&wvs[h4 * 4];
            acc += w.x * fast_tanh(qv.x + kv.x);
            acc += w.y * fast_tanh(qv.y + kv.y);
            acc += w.z * fast_tanh(qv.z + kv.z);
            acc += w.w * fast_tanh(qv.w + kv.w);
        }
        s[q][kt * TK + k] = acc;

        if (more) {
#pragma unroll
            for (int r = 0; r < 4; r++) {
                int kk = lrow + 8 * r;
                *(float4*)&kps[nxt][kk][lh4] = pre[r];
            }
        }
        __syncthreads();
    }

    // softmax over the active region only
    const int lane = k;
    const int kmax = NT * TK;

    float m = -1e30f;
    for (int j = lane; j < kmax; j += 32) {
        float x = (j < vl) ? s[q][j] : -1e30f;
        m = fmaxf(m, x);
    }
#pragma unroll
    for (int o = 16; o > 0; o >>= 1) m = fmaxf(m, __shfl_xor_sync(0xffffffffu, m, o));

    float sum = 0.f;
    for (int j = lane; j < kmax; j += 32) {
        float e = (j < vl) ? __expf(s[q][j] - m) : 0.f;
        s[q][j] = e;
        sum += e;
    }
#pragma unroll
    for (int o = 16; o > 0; o >>= 1) sum += __shfl_xor_sync(0xffffffffu, sum, o);

    const float inv = 1.f / sum;
    __nv_bfloat16* ph = g_Ph + (long long)(b * NQ + q0 + q) * NK;
    __nv_bfloat16* pl = g_Pl + (long long)(b * NQ + q0 + q) * NK;
    for (int j = lane; j < kmax; j += 32) {
        float x = s[q][j] * inv;
        __nv_bfloat16 h = __float2bfloat16(x);
        ph[j] = h;
        pl[j] = __float2bfloat16(x - __bfloat162float(h));
    }
}

// ---------------------------------------------------------------------------
extern "C" void kernel_launch(void* const* d_in, const int* in_sizes, int n_in,
                              void* d_out, int out_size)
{
    const float* Q    = (const float*)d_in[0];
    const float* K    = (const float*)d_in[1];
    const float* V    = (const float*)d_in[2];
    const float* Wq   = (const float*)d_in[3];
    const float* Wk   = (const float*)d_in[4];
    const float* wv   = (const float*)d_in[5];
    const void*  vlen = (const void*)d_in[6];
    float*       out  = (float*)d_out;

    float *pQp, *pKp;
    cudaGetSymbolAddress((void**)&pQp, g_Qp);
    cudaGetSymbolAddress((void**)&pKp, g_Kp);

    // prep: fp32 -> bf16 hi/lo splits + transposes
    {
        dim3 g(148, 1, 2);
        split_qk<<<g, 256>>>(Q, K);
    }
    {
        dim3 g((DD * HH + 255) / 256, 1, 2);
        wtrans<<<g, 256>>>(Wq, Wk);
    }
    {
        dim3 g(DD / 32, NK / 32, BB);
        vtrans<<<g, dim3(32, 8)>>>(V, vlen);
    }
    // projections on tensor cores (warp MMA): grid (2, 32, 2) = 128 CTAs
    {
        dim3 g(HH / 64, (BB * NQ) / 64, 2);
        mma_proj<<<g, 256>>>(vlen);
    }
    // scores + mask + softmax -> P
    {
        dim3 g(BB * NQ / TQ);
        scores_softmax<<<g, 256>>>(pQp, pKp, wv, vlen);
    }
    // out = P @ V: grid (8, 8, 4) = 256 CTAs
    {
        dim3 g(DD / 64, NQ / 64, BB);
        mma_pv<<<g, 256>>>(out, vlen);
    }
}

// round 7
// speedup vs baseline: 1.8798x; 1.0568x over previous
#include <cuda_runtime.h>
#include <cuda_bf16.h>
#include <cstdint>

#define BB   4
#define NQ   512
#define NK   512
#define DD   512
#define HH   128

#define TQ   8
#define TK   32
#define HPAD 132

// ---------------- scratch (allocation-free device globals) ----------------
__device__ float g_Qp[BB * NQ * HH];
__device__ float g_Kp[BB * NK * HH];
__device__ __nv_bfloat16 g_Qh[BB * NQ * DD], g_Ql[BB * NQ * DD];
__device__ __nv_bfloat16 g_Kh[BB * NK * DD], g_Kl[BB * NK * DD];
__device__ __nv_bfloat16 g_Wqth[HH * DD], g_Wqtl[HH * DD];   // W^T [128][512]
__device__ __nv_bfloat16 g_Wkth[HH * DD], g_Wktl[HH * DD];
__device__ __nv_bfloat16 g_Vth[BB * DD * NK], g_Vtl[BB * DD * NK]; // V^T [n][k]
__device__ __nv_bfloat16 g_Ph[BB * NQ * NK], g_Pl[BB * NQ * NK];

__device__ __forceinline__ float fast_tanh(float x) {
    float y;
    asm("tanh.approx.f32 %0, %1;" : "=f"(y) : "f"(x));
    return y;
}

__device__ __forceinline__ long long read_vlen(const void* p, int b) {
    const int* w = (const int*)p;
    bool is64 = (w[1] == 0) && (w[3] == 0);
    if (is64) return ((const long long*)p)[b];
    return (long long)w[b];
}

__device__ __forceinline__ uint32_t smem_u32(const void* p) {
    uint32_t a;
    asm("{ .reg .u64 t; cvta.to.shared.u64 t, %1; cvt.u32.u64 %0, t; }" : "=r"(a) : "l"(p));
    return a;
}

__device__ __forceinline__ void ldmx4(uint32_t* r, uint32_t addr) {
    asm volatile("ldmatrix.sync.aligned.m8n8.x4.shared.b16 {%0,%1,%2,%3}, [%4];"
        : "=r"(r[0]), "=r"(r[1]), "=r"(r[2]), "=r"(r[3]) : "r"(addr));
}

__device__ __forceinline__ void mma16816(float* d, const uint32_t* a, const uint32_t* b) {
    asm volatile("mma.sync.aligned.m16n8k16.row.col.f32.bf16.bf16.f32 "
        "{%0,%1,%2,%3}, {%4,%5,%6,%7}, {%8,%9}, {%0,%1,%2,%3};"
        : "+f"(d[0]), "+f"(d[1]), "+f"(d[2]), "+f"(d[3])
        : "r"(a[0]), "r"(a[1]), "r"(a[2]), "r"(a[3]), "r"(b[0]), "r"(b[1]));
}

__device__ __forceinline__ void cpa16(uint32_t dst, const void* src) {
    asm volatile("cp.async.cg.shared.global [%0], [%1], 16;" :: "r"(dst), "l"(src));
}
#define CP_COMMIT() asm volatile("cp.async.commit_group;" ::: "memory")

// ---------------- conversion / transpose kernels ----------------
__global__ void split_qk(const float* __restrict__ Q, const float* __restrict__ K)
{
    const float* in = blockIdx.z ? K : Q;
    __nv_bfloat16* hi = blockIdx.z ? g_Kh : g_Qh;
    __nv_bfloat16* lo = blockIdx.z ? g_Kl : g_Ql;
    const int n4 = (BB * NQ * DD) / 4;
    for (int i = blockIdx.x * blockDim.x + threadIdx.x; i < n4; i += gridDim.x * blockDim.x) {
        float4 v = ((const float4*)in)[i];
        __nv_bfloat16 hx = __float2bfloat16(v.x), hy = __float2bfloat16(v.y);
        __nv_bfloat16 hz = __float2bfloat16(v.z), hw = __float2bfloat16(v.w);
        ((__nv_bfloat162*)hi)[i * 2 + 0] = __nv_bfloat162(hx, hy);
        ((__nv_bfloat162*)hi)[i * 2 + 1] = __nv_bfloat162(hz, hw);
        ((__nv_bfloat162*)lo)[i * 2 + 0] = __nv_bfloat162(
            __float2bfloat16(v.x - __bfloat162float(hx)), __float2bfloat16(v.y - __bfloat162float(hy)));
        ((__nv_bfloat162*)lo)[i * 2 + 1] = __nv_bfloat162(
            __float2bfloat16(v.z - __bfloat162float(hz)), __float2bfloat16(v.w - __bfloat162float(hw)));
    }
}

__global__ void wtrans(const float* __restrict__ Wq, const float* __restrict__ Wk)
{
    const float* W = blockIdx.z ? Wk : Wq;
    __nv_bfloat16* th = blockIdx.z ? g_Wkth : g_Wqth;
    __nv_bfloat16* tl = blockIdx.z ? g_Wktl : g_Wqtl;
    int i = blockIdx.x * blockDim.x + threadIdx.x;
    if (i < DD * HH) {
        int k = i >> 7, n = i & 127;
        float v = W[i];
        __nv_bfloat16 h = __float2bfloat16(v);
        th[n * DD + k] = h;
        tl[n * DD + k] = __float2bfloat16(v - __bfloat162float(h));
    }
}

// V[b][k][n] -> Vt[b][n][k]; skip k-tiles entirely beyond valid length.
__global__ void vtrans(const float* __restrict__ V, const void* __restrict__ vlen)
{
    __shared__ float t[32][33];
    const int b  = blockIdx.z;
    const int k0 = blockIdx.y * 32;
    if ((long long)k0 >= read_vlen(vlen, b)) return;
    const int n0 = blockIdx.x * 32;
    const int tx = threadIdx.x, ty = threadIdx.y;   // (32, 8)
    const float* Vb = V + (long long)b * NK * DD;
#pragma unroll
    for (int r = 0; r < 4; r++)
        t[ty + r * 8][tx] = Vb[(long long)(k0 + ty + r * 8) * DD + n0 + tx];
    __syncthreads();
    __nv_bfloat16* th = g_Vth + (long long)b * DD * NK;
    __nv_bfloat16* tl = g_Vtl + (long long)b * DD * NK;
#pragma unroll
    for (int r = 0; r < 4; r++) {
        float v = t[tx][ty + r * 8];
        __nv_bfloat16 h = __float2bfloat16(v);
        th[(long long)(n0 + ty + r * 8) * NK + k0 + tx] = h;
        tl[(long long)(n0 + ty + r * 8) * NK + k0 + tx] = __float2bfloat16(v - __bfloat162float(h));
    }
}

// ---------------- warp-MMA bf16x3 GEMM: C[64x64] = A[64xK] @ B[64xK]^T -----
// 256 threads = 8 warps (4m x 2n). Rows padded to 80B -> conflict-free ldmatrix.
// 4-stage cp.async pipeline (80KB dynamic smem).
#define STG  20480
#define O_AH 0
#define O_AL 5120
#define O_BH 10240
#define O_BL 15360
#define NSTG 4
#define MMA_DSMEM (NSTG * STG)

__device__ __forceinline__ void mma_gemm(
    const __nv_bfloat16* __restrict__ Ah, const __nv_bfloat16* __restrict__ Al,
    const __nv_bfloat16* __restrict__ Bh, const __nv_bfloat16* __restrict__ Bl,
    float* __restrict__ C, int lda, int ldb, int ldc,
    int m0, int n0, int nstages)
{
    extern __shared__ __align__(128) char smem[];
    const uint32_t sb = smem_u32(smem);
    const int tid  = threadIdx.x;
    const int lane = tid & 31;
    const int w    = tid >> 5;
    const int wm   = w & 3;
    const int wn   = w >> 2;

    const int lrow = tid >> 2;
    const int lchk = tid & 3;
    const __nv_bfloat16* pAh = Ah + (long long)(m0 + lrow) * lda + lchk * 8;
    const __nv_bfloat16* pAl = Al + (long long)(m0 + lrow) * lda + lchk * 8;
    const __nv_bfloat16* pBh = Bh + (long long)(n0 + lrow) * ldb + lchk * 8;
    const __nv_bfloat16* pBl = Bl + (long long)(n0 + lrow) * ldb + lchk * 8;
    const uint32_t stO = lrow * 80 + lchk * 16;

    const uint32_t aOff = (wm * 16 + (lane & 15)) * 80 + (lane >> 4) * 16;
    const int jj = lane >> 3;
    const uint32_t bOff = (wn * 32 + (jj >> 1) * 8 + (lane & 7)) * 80 + (jj & 1) * 16;

    float acc[4][4] = {};

    // prologue: issue stages 0..NSTG-2
#pragma unroll
    for (int s = 0; s < NSTG - 1; s++) {
        if (s < nstages) {
            uint32_t d = sb + s * STG + stO;
            cpa16(d + O_AH, pAh + s * 32);
            cpa16(d + O_AL, pAl + s * 32);
            cpa16(d + O_BH, pBh + s * 32);
            cpa16(d + O_BL, pBl + s * 32);
        }
        CP_COMMIT();
    }

    for (int t = 0; t < nstages; t++) {
        asm volatile("cp.async.wait_group %0;" :: "n"(NSTG - 2) : "memory");
        __syncthreads();

        // issue stage t+NSTG-1 into buffer (t-1)%NSTG (safe: consumed pre-sync)
        {
            int s = t + NSTG - 1;
            if (s < nstages) {
                uint32_t d = sb + (uint32_t)(s & (NSTG - 1)) * STG + stO;
                cpa16(d + O_AH, pAh + s * 32);
                cpa16(d + O_AL, pAl + s * 32);
                cpa16(d + O_BH, pBh + s * 32);
                cpa16(d + O_BL, pBl + s * 32);
            }
            CP_COMMIT();
        }

        const uint32_t cur = sb + (uint32_t)(t & (NSTG - 1)) * STG;
#pragma unroll
        for (int ks = 0; ks < 2; ks++) {
            uint32_t ah[4], al[4];
            ldmx4(ah, cur + O_AH + aOff + ks * 32);
            ldmx4(al, cur + O_AL + aOff + ks * 32);
#pragma unroll
            for (int np = 0; np < 2; np++) {
                uint32_t bh[4], bl[4];
                ldmx4(bh, cur + O_BH + bOff + np * 1280 + ks * 32);
                ldmx4(bl, cur + O_BL + bOff + np * 1280 + ks * 32);
                mma16816(acc[2 * np + 0], ah, bh);
                mma16816(acc[2 * np + 1], ah, bh + 2);
                mma16816(acc[2 * np + 0], ah, bl);
                mma16816(acc[2 * np + 1], ah, bl + 2);
                mma16816(acc[2 * np + 0], al, bh);
                mma16816(acc[2 * np + 1], al, bh + 2);
            }
        }
    }

    const int rr = m0 + wm * 16 + (lane >> 2);
    const int cc = n0 + wn * 32 + (lane & 3) * 2;
#pragma unroll
    for (int nt = 0; nt < 4; nt++) {
        *(float2*)&C[(long long)rr * ldc + cc + nt * 8]       = make_float2(acc[nt][0], acc[nt][1]);
        *(float2*)&C[(long long)(rr + 8) * ldc + cc + nt * 8] = make_float2(acc[nt][2], acc[nt][3]);
    }
}

// z=0: Qp = Q@Wq (all rows); z=1: Kp = K@Wk (skip fully-masked row blocks)
__global__ __launch_bounds__(256)
void mma_proj(const void* __restrict__ vlen)
{
    const int n0 = blockIdx.x * 64;
    const int m0 = blockIdx.y * 64;
    if (blockIdx.z == 0) {
        mma_gemm(g_Qh, g_Ql, g_Wqth, g_Wqtl, g_Qp, DD, DD, HH, m0, n0, DD / 32);
    } else {
        if ((long long)(m0 & (NK - 1)) >= read_vlen(vlen, m0 >> 9)) return;
        mma_gemm(g_Kh, g_Kl, g_Wkth, g_Wktl, g_Kp, DD, DD, HH, m0, n0, DD / 32);
    }
}

// out[b] = P[b] @ V[b]; K-loop bounded by valid length (P==0 beyond).
__global__ __launch_bounds__(256)
void mma_pv(float* __restrict__ out, const void* __restrict__ vlen)
{
    const int b = blockIdx.z;
    const long long vl = read_vlen(vlen, b);
    const int ns = (int)((vl + 31) >> 5);
    mma_gemm(g_Ph + (long long)b * NQ * NK, g_Pl + (long long)b * NQ * NK,
             g_Vth + (long long)b * DD * NK, g_Vtl + (long long)b * DD * NK,
             out + (long long)b * NQ * DD,
             NK, NK, DD, blockIdx.y * 64, blockIdx.x * 64, ns);
}

// ---------------- fused scores + mask + softmax -> P (bf16 hi/lo) ----------
__global__ __launch_bounds__(256)
void scores_softmax(const float* __restrict__ Qp, const float* __restrict__ Kp,
                    const float* __restrict__ wv, const void* __restrict__ vlen)
{
    __shared__ float qps[TQ][HPAD];
    __shared__ float kps[2][TK][HPAD];
    __shared__ float wvs[HH];
    __shared__ float s[TQ][NK];

    const int tid = threadIdx.x;
    const int bx  = blockIdx.x;
    const int b   = bx / (NQ / TQ);
    const int q0  = (bx % (NQ / TQ)) * TQ;

    const long long vl = read_vlen(vlen, b);
    const int NT = (int)((vl + TK - 1) / TK);

    if (tid < HH) wvs[tid] = wv[tid];

    {
        const int q  = tid >> 5;
        const int h4 = (tid & 31) * 4;
        float4 v = *(const float4*)&Qp[(long long)(b * NQ + q0 + q) * HH + h4];
        *(float4*)&qps[q][h4] = v;
    }

    const int q = tid >> 5;
    const int k = tid & 31;

    const float* kbase = &Kp[(long long)b * NK * HH];
    const int lrow = tid >> 5;
    const int lh4  = (tid & 31) * 4;

#pragma unroll
    for (int r = 0; r < 4; r++) {
        int kk = lrow + 8 * r;
        float4 v = *(const float4*)&kbase[(long long)kk * HH + lh4];
        *(float4*)&kps[0][kk][lh4] = v;
    }
    __syncthreads();

    for (int kt = 0; kt < NT; kt++) {
        const int cur = kt & 1;
        const int nxt = cur ^ 1;
        float4 pre[4];
        const bool more = (kt + 1 < NT);
        if (more) {
#pragma unroll
            for (int r = 0; r < 4; r++) {
                int kk = lrow + 8 * r;
                pre[r] = *(const float4*)&kbase[(long long)((kt + 1) * TK + kk) * HH + lh4];
            }
        }

        float acc = 0.f;
#pragma unroll 8
        for (int h4 = 0; h4 < HH / 4; h4++) {
            float4 kv = *(const float4*)&kps[cur][k][h4 * 4];
            float4 qv = *(const float4*)&qps[q][h4 * 4];
            float4 w  = *(const float4*)&wvs[h4 * 4];
            acc += w.x * fast_tanh(qv.x + kv.x);
            acc += w.y * fast_tanh(qv.y + kv.y);
            acc += w.z * fast_tanh(qv.z + kv.z);
            acc += w.w * fast_tanh(qv.w + kv.w);
        }
        s[q][kt * TK + k] = acc;

        if (more) {
#pragma unroll
            for (int r = 0; r < 4; r++) {
                int kk = lrow + 8 * r;
                *(float4*)&kps[nxt][kk][lh4] = pre[r];
            }
        }
        __syncthreads();
    }

    const int lane = k;
    const int kmax = NT * TK;

    float m = -1e30f;
    for (int j = lane; j < kmax; j += 32) {
        float x = (j < vl) ? s[q][j] : -1e30f;
        m = fmaxf(m, x);
    }
#pragma unroll
    for (int o = 16; o > 0; o >>= 1) m = fmaxf(m, __shfl_xor_sync(0xffffffffu, m, o));

    float sum = 0.f;
    for (int j = lane; j < kmax; j += 32) {
        float e = (j < vl) ? __expf(s[q][j] - m) : 0.f;
        s[q][j] = e;
        sum += e;
    }
#pragma unroll
    for (int o = 16; o > 0; o >>= 1) sum += __shfl_xor_sync(0xffffffffu, sum, o);

    const float inv = 1.f / sum;
    __nv_bfloat16* ph = g_Ph + (long long)(b * NQ + q0 + q) * NK;
    __nv_bfloat16* pl = g_Pl + (long long)(b * NQ + q0 + q) * NK;
    for (int j = lane; j < kmax; j += 32) {
        float x = s[q][j] * inv;
        __nv_bfloat16 h = __float2bfloat16(x);
        ph[j] = h;
        pl[j] = __float2bfloat16(x - __bfloat162float(h));
    }
}

// ---------------------------------------------------------------------------
extern "C" void kernel_launch(void* const* d_in, const int* in_sizes, int n_in,
                              void* d_out, int out_size)
{
    const float* Q    = (const float*)d_in[0];
    const float* K    = (const float*)d_in[1];
    const float* V    = (const float*)d_in[2];
    const float* Wq   = (const float*)d_in[3];
    const float* Wk   = (const float*)d_in[4];
    const float* wv   = (const float*)d_in[5];
    const void*  vlen = (const void*)d_in[6];
    float*       out  = (float*)d_out;

    float *pQp, *pKp;
    cudaGetSymbolAddress((void**)&pQp, g_Qp);
    cudaGetSymbolAddress((void**)&pKp, g_Kp);

    static bool attr_done = false;
    if (!attr_done) {
        cudaFuncSetAttribute(mma_proj, cudaFuncAttributeMaxDynamicSharedMemorySize, MMA_DSMEM);
        cudaFuncSetAttribute(mma_pv,   cudaFuncAttributeMaxDynamicSharedMemorySize, MMA_DSMEM);
        attr_done = true;
    }

    // prep: fp32 -> bf16 hi/lo splits + transposes
    {
        dim3 g(148, 1, 2);
        split_qk<<<g, 256>>>(Q, K);
    }
    {
        dim3 g((DD * HH + 255) / 256, 1, 2);
        wtrans<<<g, 256>>>(Wq, Wk);
    }
    {
        dim3 g(DD / 32, NK / 32, BB);
        vtrans<<<g, dim3(32, 8)>>>(V, vlen);
    }
    // projections (warp MMA, 4-stage cp.async): grid (2, 32, 2) = 128 CTAs
    {
        dim3 g(HH / 64, (BB * NQ) / 64, 2);
        mma_proj<<<g, 256, MMA_DSMEM>>>(vlen);
    }
    // scores + mask + softmax -> P
    {
        dim3 g(BB * NQ / TQ);
        scores_softmax<<<g, 256>>>(pQp, pKp, wv, vlen);
    }
    // out = P @ V: grid (8, 8, 4) = 256 CTAs
    {
        dim3 g(DD / 64, NQ / 64, BB);
        mma_pv<<<g, 256, MMA_DSMEM>>>(out, vlen);
    }
}